// round 12
// baseline (speedup 1.0000x reference)
#include <cuda_runtime.h>
#include <math.h>

// Problem constants (from reference)
constexpr int Nn  = 100000;
constexpr int Ee  = 3200000;
constexpr int ET  = Nn + Ee;       // edges + self loops
constexpr int FIN = 165;
constexpr int HID = 64;

// ---------------- scratch (static device allocations; no cudaMalloc) ----------------
__device__ float g_xl1[(size_t)Nn * HID];
__device__ float g_xr1[(size_t)Nn * HID];
__device__ float g_h  [(size_t)Nn * HID];   // x@Wlin1+blin1 (lin skip)
__device__ float g_xl2[Nn * 2];
__device__ float g_xr2[Nn * 2];
__device__ float g_lin2[Nn * 2];
__device__ int   g_deg[Nn];
__device__ int   g_incl[Nn];
__device__ int   g_rowptr[Nn + 1];
__device__ int   g_cursor[Nn];
__device__ int   g_bsum[128];
__device__ int   g_boff[128];
__device__ int   g_col[ET];

// Packed f32x2 FMA (Blackwell): acc = w * x + acc on a 64-bit register pair.
#define FMA2(acc, w, xp) \
    asm("fma.rn.f32x2 %0, %1, %2, %0;" : "+l"(acc) : "l"(w), "l"(xp))
#define PACK_DUP(xp, xv) \
    asm("mov.b64 %0, {%1, %1};" : "=l"(xp) : "f"(xv))
#define UNPACK2(lo, hi, p) \
    asm("mov.b64 {%0, %1}, %2;" : "=f"(lo), "=f"(hi) : "l"(p))

__device__ __forceinline__ void cp_async16(void* dst_smem, const void* src_gmem) {
    unsigned saddr = (unsigned)__cvta_generic_to_shared(dst_smem);
    asm volatile("cp.async.ca.shared.global [%0], [%1], 16;" :: "r"(saddr), "l"(src_gmem));
}
__device__ __forceinline__ void cp_async_commit() {
    asm volatile("cp.async.commit_group;");
}
__device__ __forceinline__ void cp_async_wait0() {
    asm volatile("cp.async.wait_group 0;");
}

// ---------------- K0: init degrees (self loop => start at 1) ----------------
__global__ void k_init_deg() {
    int i = blockIdx.x * blockDim.x + threadIdx.x;
    if (i < Nn) g_deg[i] = 1;
}

// ---------------- K1: fused layer-1 triple GEMM (FFMA2 + cp.async double buffer) ----------------
constexpr int G1_THREADS = 384;                 // 24 col-threads x 16 node-threads
constexpr int XBUF = 64 * FIN;                  // floats per X buffer
constexpr int G1_SMEM = (FIN * 192 + 2 * XBUF) * 4;   // 211,200 B

__global__ __launch_bounds__(G1_THREADS, 1)
void k_gemm1(const float* __restrict__ x,
             const float* __restrict__ Wl, const float* __restrict__ Wr,
             const float* __restrict__ Wlin, const float* __restrict__ blin) {
    extern __shared__ float sm[];
    float* Wsh = sm;                  // [165][192]
    float* Xsh = sm + FIN * 192;      // 2 x [64][165]
    int tid = threadIdx.x;

    for (int idx = tid; idx < FIN * 192; idx += G1_THREADS) {
        int k = idx / 192, c = idx % 192;
        float v = (c < 64) ? Wl[k * 64 + c]
                : (c < 128) ? Wr[k * 64 + (c - 64)]
                : Wlin[k * 64 + (c - 128)];
        Wsh[idx] = v;
    }

    int ct = tid % 24;                // col group: 8 cols each
    int nt = tid / 24;                // node group: 4 nodes each (nt 0..15)
    int cbase = ct * 8;
    int region = cbase >> 6;          // 0: xl1, 1: xr1, 2: lin
    int coff = cbase & 63;

    float bias_r[8];
#pragma unroll
    for (int q = 0; q < 8; q++) bias_r[q] = (region == 2) ? blin[coff + q] : 0.0f;

    const ulonglong2* W2 = (const ulonglong2*)Wsh;   // 16B = 2 packed f32 pairs
    constexpr int NTILES = (Nn + 63) / 64;   // 1563 (last tile has 32 rows)

    // async preload of first tile
    int tile = blockIdx.x;
    if (tile < NTILES) {
        int row0 = tile * 64;
        int rows = (Nn - row0 < 64) ? (Nn - row0) : 64;
        const float4* src = (const float4*)(x + (size_t)row0 * FIN);
        float4* dst = (float4*)Xsh;
        int nload = (rows * FIN) / 4;
        for (int idx = tid; idx < nload; idx += G1_THREADS)
            cp_async16(dst + idx, src + idx);
    }
    cp_async_commit();

    int buf = 0;
    for (; tile < NTILES; tile += gridDim.x) {
        cp_async_wait0();
        __syncthreads();              // buffer `buf` ready; W ready (first iter)

        // kick off next tile into the other buffer
        int next = tile + gridDim.x;
        if (next < NTILES) {
            int nrow0 = next * 64;
            int nrows = (Nn - nrow0 < 64) ? (Nn - nrow0) : 64;
            const float4* src = (const float4*)(x + (size_t)nrow0 * FIN);
            float4* dst = (float4*)(Xsh + (buf ^ 1) * XBUF);
            int nload = (nrows * FIN) / 4;
            for (int idx = tid; idx < nload; idx += G1_THREADS)
                cp_async16(dst + idx, src + idx);
        }
        cp_async_commit();

        int row0 = tile * 64;
        const float* XB = Xsh + buf * XBUF;

        unsigned long long acc2[4][4];
#pragma unroll
        for (int n = 0; n < 4; n++)
#pragma unroll
            for (int q = 0; q < 4; q++) acc2[n][q] = 0ULL;

        const float* xr0 = XB + (nt * 4 + 0) * FIN;
        const float* xr1 = XB + (nt * 4 + 1) * FIN;
        const float* xr2 = XB + (nt * 4 + 2) * FIN;
        const float* xr3 = XB + (nt * 4 + 3) * FIN;

#pragma unroll 3
        for (int k = 0; k < FIN; k++) {
            unsigned long long xp0, xp1, xp2, xp3;
            PACK_DUP(xp0, xr0[k]);
            PACK_DUP(xp1, xr1[k]);
            PACK_DUP(xp2, xr2[k]);
            PACK_DUP(xp3, xr3[k]);
            ulonglong2 wA = W2[k * 48 + ct * 2];       // cols c0c1 | c2c3
            ulonglong2 wB = W2[k * 48 + ct * 2 + 1];   // cols c4c5 | c6c7
            FMA2(acc2[0][0], wA.x, xp0); FMA2(acc2[0][1], wA.y, xp0);
            FMA2(acc2[0][2], wB.x, xp0); FMA2(acc2[0][3], wB.y, xp0);
            FMA2(acc2[1][0], wA.x, xp1); FMA2(acc2[1][1], wA.y, xp1);
            FMA2(acc2[1][2], wB.x, xp1); FMA2(acc2[1][3], wB.y, xp1);
            FMA2(acc2[2][0], wA.x, xp2); FMA2(acc2[2][1], wA.y, xp2);
            FMA2(acc2[2][2], wB.x, xp2); FMA2(acc2[2][3], wB.y, xp2);
            FMA2(acc2[3][0], wA.x, xp3); FMA2(acc2[3][1], wA.y, xp3);
            FMA2(acc2[3][2], wB.x, xp3); FMA2(acc2[3][3], wB.y, xp3);
        }

#pragma unroll
        for (int n = 0; n < 4; n++) {
            int ng = row0 + nt * 4 + n;
            if (ng < Nn) {
                float a0, a1, a2, a3, a4, a5, a6, a7;
                UNPACK2(a0, a1, acc2[n][0]);
                UNPACK2(a2, a3, acc2[n][1]);
                UNPACK2(a4, a5, acc2[n][2]);
                UNPACK2(a6, a7, acc2[n][3]);
                float* base = (region == 0) ? g_xl1 : (region == 1) ? g_xr1 : g_h;
                base += (size_t)ng * 64 + coff;
                float4 v0 = make_float4(a0 + bias_r[0], a1 + bias_r[1],
                                        a2 + bias_r[2], a3 + bias_r[3]);
                float4 v1 = make_float4(a4 + bias_r[4], a5 + bias_r[5],
                                        a6 + bias_r[6], a7 + bias_r[7]);
                ((float4*)base)[0] = v0;
                ((float4*)base)[1] = v1;
            }
        }
        __syncthreads();              // all compute on `buf` done before it is refilled
        buf ^= 1;
    }
}

// ---------------- K2: degree histogram over real edges ----------------
__global__ void k_deg(const int* __restrict__ ei) {
    int i = blockIdx.x * blockDim.x + threadIdx.x;
    if (i < Ee) {
        int d = ei[Ee + i];     // dst row
        atomicAdd(&g_deg[d], 1);
    }
}

// ---------------- K3: 3-phase exclusive scan -> rowptr, cursor ----------------
__global__ __launch_bounds__(1024) void k_scan1() {
    __shared__ int s[1024];
    int tid = threadIdx.x;
    int i = blockIdx.x * 1024 + tid;
    int v = (i < Nn) ? g_deg[i] : 0;
    s[tid] = v;
    __syncthreads();
    for (int off = 1; off < 1024; off <<= 1) {
        int t = (tid >= off) ? s[tid - off] : 0;
        __syncthreads();
        s[tid] += t;
        __syncthreads();
    }
    if (i < Nn) g_incl[i] = s[tid];
    if (tid == 1023) g_bsum[blockIdx.x] = s[tid];
}

__global__ void k_scan2(int nb) {
    __shared__ int s[128];
    int tid = threadIdx.x;
    int v = (tid < nb) ? g_bsum[tid] : 0;
    s[tid] = v;
    __syncthreads();
    for (int off = 1; off < 128; off <<= 1) {
        int t = (tid >= off) ? s[tid - off] : 0;
        __syncthreads();
        s[tid] += t;
        __syncthreads();
    }
    g_boff[tid] = s[tid] - v;   // exclusive
}

__global__ void k_scan3() {
    int i = blockIdx.x * blockDim.x + threadIdx.x;
    if (i < Nn) {
        int r = g_incl[i] + g_boff[i >> 10];
        g_rowptr[i + 1] = r;
        g_cursor[i] = r - g_deg[i];    // == rowptr[i]
        if (i == 0) g_rowptr[0] = 0;
    }
}

// ---------------- K4: scatter edges + self loops into CSR ----------------
__global__ void k_scatter(const int* __restrict__ ei) {
    int i = blockIdx.x * blockDim.x + threadIdx.x;
    if (i >= ET) return;
    int s, d;
    if (i < Ee) { s = ei[i]; d = ei[Ee + i]; }
    else        { s = d = i - Ee; }
    int pos = atomicAdd(&g_cursor[d], 1);
    g_col[pos] = s;
}

// ---------------- K5: layer-1 attention + FUSED layer-2 transforms ----------------
// Half-warp slots as R9 (measured best). After the xor-16 merge both halves hold
// identical (m,s,A); epilogue computes h in registers and directly produces
// xl2/xr2/lin2 (h @ W2 dots, reduced within each 16-lane half). g_h is never
// written with h — only read for the lin skip.
__global__ __launch_bounds__(256, 5)
void k_att1(const float* __restrict__ att, const float* __restrict__ b1,
            const float* __restrict__ Wl2, const float* __restrict__ Wr2,
            const float* __restrict__ Wlin2, const float* __restrict__ blin2) {
    int gt = blockIdx.x * blockDim.x + threadIdx.x;
    int i = gt >> 5;
    int lane = gt & 31;
    if (i >= Nn) return;
    int half = lane >> 4;     // edge slot 0/1
    int g = lane & 15;        // channel group (4 channels)

    int e0 = g_rowptr[i], e1 = g_rowptr[i + 1];

    float4 r = ((const float4*)(g_xr1 + (size_t)i * 64))[g];
    float4 a = ((const float4*)att)[g];

    float m = -1e30f, s = 0.f;
    float A0 = 0.f, A1 = 0.f, A2 = 0.f, A3 = 0.f;

    for (int base = e0; base < e1; base += 2) {
        int idx = base + half;
        bool act = idx < e1;
        int j = act ? g_col[idx] : 0;
        float4 u = ((const float4*)(g_xl1 + (size_t)j * 64))[g];

        float t0 = u.x + r.x; t0 = (t0 > 0.f) ? t0 : 0.2f * t0;
        float t1 = u.y + r.y; t1 = (t1 > 0.f) ? t1 : 0.2f * t1;
        float t2 = u.z + r.z; t2 = (t2 > 0.f) ? t2 : 0.2f * t2;
        float t3 = u.w + r.w; t3 = (t3 > 0.f) ? t3 : 0.2f * t3;
        float p = t0 * a.x + t1 * a.y + t2 * a.z + t3 * a.w;
        // reduce within the 16-lane half (xor 1,2,4,8 keeps bit 4)
        p += __shfl_xor_sync(0xffffffffu, p, 1);
        p += __shfl_xor_sync(0xffffffffu, p, 2);
        p += __shfl_xor_sync(0xffffffffu, p, 4);
        p += __shfl_xor_sync(0xffffffffu, p, 8);

        if (act) {
            if (p > m) {
                float sc = __expf(m - p);
                s *= sc; A0 *= sc; A1 *= sc; A2 *= sc; A3 *= sc;
                m = p;
            }
            float w = __expf(p - m);
            s += w;
            A0 += w * u.x; A1 += w * u.y; A2 += w * u.z; A3 += w * u.w;
        }
    }

    // merge the two half-states (xor 16) — both halves end with identical state
    {
        float mo  = __shfl_xor_sync(0xffffffffu, m, 16);
        float so  = __shfl_xor_sync(0xffffffffu, s, 16);
        float B0  = __shfl_xor_sync(0xffffffffu, A0, 16);
        float B1  = __shfl_xor_sync(0xffffffffu, A1, 16);
        float B2  = __shfl_xor_sync(0xffffffffu, A2, 16);
        float B3  = __shfl_xor_sync(0xffffffffu, A3, 16);
        float mn = fmaxf(m, mo);
        float c1 = __expf(m - mn);
        float c2 = __expf(mo - mn);
        s  = s * c1 + so * c2;
        A0 = A0 * c1 + B0 * c2;
        A1 = A1 * c1 + B1 * c2;
        A2 = A2 * c1 + B2 * c2;
        A3 = A3 * c1 + B3 * c2;
    }

    // h channels [4g..4g+4) in registers (all lanes; duplicated across halves)
    float inv = 1.0f / s;
    float4 bb = ((const float4*)b1)[g];
    float4 hl = ((const float4*)(g_h + (size_t)i * 64))[g];
    float o0 = A0 * inv + bb.x + hl.x;
    float o1 = A1 * inv + bb.y + hl.y;
    float o2 = A2 * inv + bb.z + hl.z;
    float o3 = A3 * inv + bb.w + hl.w;
    o0 = (o0 > 0.f) ? o0 : (__expf(o0) - 1.0f);   // ELU
    o1 = (o1 > 0.f) ? o1 : (__expf(o1) - 1.0f);
    o2 = (o2 > 0.f) ? o2 : (__expf(o2) - 1.0f);
    o3 = (o3 > 0.f) ? o3 : (__expf(o3) - 1.0f);

    // fused layer-2 transforms: partial dots over this lane's 4 channels
    const float2* WlV = (const float2*)Wl2;    // [64] float2
    const float2* WrV = (const float2*)Wr2;
    const float2* WnV = (const float2*)Wlin2;
    int c = g * 4;
    float2 wl0 = WlV[c], wl1 = WlV[c + 1], wl2v = WlV[c + 2], wl3 = WlV[c + 3];
    float2 wr0 = WrV[c], wr1 = WrV[c + 1], wr2v = WrV[c + 2], wr3 = WrV[c + 3];
    float2 wn0 = WnV[c], wn1 = WnV[c + 1], wn2v = WnV[c + 2], wn3 = WnV[c + 3];
    float xl_0 = o0 * wl0.x + o1 * wl1.x + o2 * wl2v.x + o3 * wl3.x;
    float xl_1 = o0 * wl0.y + o1 * wl1.y + o2 * wl2v.y + o3 * wl3.y;
    float xr_0 = o0 * wr0.x + o1 * wr1.x + o2 * wr2v.x + o3 * wr3.x;
    float xr_1 = o0 * wr0.y + o1 * wr1.y + o2 * wr2v.y + o3 * wr3.y;
    float ln_0 = o0 * wn0.x + o1 * wn1.x + o2 * wn2v.x + o3 * wn3.x;
    float ln_1 = o0 * wn0.y + o1 * wn1.y + o2 * wn2v.y + o3 * wn3.y;
    // reduce the 6 partials within each 16-lane half
#pragma unroll
    for (int o = 1; o <= 8; o <<= 1) {
        xl_0 += __shfl_xor_sync(0xffffffffu, xl_0, o);
        xl_1 += __shfl_xor_sync(0xffffffffu, xl_1, o);
        xr_0 += __shfl_xor_sync(0xffffffffu, xr_0, o);
        xr_1 += __shfl_xor_sync(0xffffffffu, xr_1, o);
        ln_0 += __shfl_xor_sync(0xffffffffu, ln_0, o);
        ln_1 += __shfl_xor_sync(0xffffffffu, ln_1, o);
    }
    if (lane == 0) {
        ((float2*)g_xl2)[i] = make_float2(xl_0, xl_1);
        ((float2*)g_xr2)[i] = make_float2(xr_0, xr_1);
        ((float2*)g_lin2)[i] = make_float2(ln_0 + blin2[0], ln_1 + blin2[1]);
    }
}

// ---------------- K7: layer-2 attention, SINGLE PASS + log_softmax ----------------
__global__ void k_att2(const float* __restrict__ att2, const float* __restrict__ b2,
                       float* __restrict__ out) {
    int gt = blockIdx.x * blockDim.x + threadIdx.x;
    int i = gt >> 5;
    int lane = gt & 31;
    if (i >= Nn) return;

    int e0 = g_rowptr[i], e1 = g_rowptr[i + 1];
    const float2* xl2v = (const float2*)g_xl2;
    float2 xr = ((const float2*)g_xr2)[i];
    float a0 = att2[0], a1 = att2[1];

    float m = -1e30f, s = 0.f, A0 = 0.f, A1 = 0.f;
    for (int base = e0; base < e1; base += 32) {
        int idx = base + lane;
        if (idx < e1) {
            int j = g_col[idx];
            float2 xj = xl2v[j];
            float h0 = xj.x + xr.x; h0 = (h0 > 0.f) ? h0 : 0.2f * h0;
            float h1 = xj.y + xr.y; h1 = (h1 > 0.f) ? h1 : 0.2f * h1;
            float e = a0 * h0 + a1 * h1;
            if (e > m) { float sc = __expf(m - e); s *= sc; A0 *= sc; A1 *= sc; m = e; }
            float w = __expf(e - m);
            s += w; A0 += w * xj.x; A1 += w * xj.y;
        }
    }
    // merge lanes with rescale
#pragma unroll
    for (int o = 16; o; o >>= 1) {
        float mo  = __shfl_xor_sync(0xffffffffu, m, o);
        float so  = __shfl_xor_sync(0xffffffffu, s, o);
        float A0o = __shfl_xor_sync(0xffffffffu, A0, o);
        float A1o = __shfl_xor_sync(0xffffffffu, A1, o);
        float mn = fmaxf(m, mo);
        float sc1 = __expf(m - mn);
        float sc2 = __expf(mo - mn);
        s  = s * sc1 + so * sc2;
        A0 = A0 * sc1 + A0o * sc2;
        A1 = A1 * sc1 + A1o * sc2;
        m = mn;
    }

    if (lane == 0) {
        float inv = 1.0f / s;
        float2 ln = ((const float2*)g_lin2)[i];
        float z0 = A0 * inv + b2[0] + ln.x;
        float z1 = A1 * inv + b2[1] + ln.y;
        float zm = fmaxf(z0, z1);
        float l = zm + __logf(__expf(z0 - zm) + __expf(z1 - zm));
        ((float2*)out)[i] = make_float2(z0 - l, z1 - l);
    }
}

// ---------------- K8: edge_index passthrough as float32 values ----------------
__global__ void k_cast_edges(const int* __restrict__ ei, float* __restrict__ out, int n) {
    int i = blockIdx.x * blockDim.x + threadIdx.x;
    if (i < n) out[i] = (float)ei[i];
}

// ---------------- launcher: fork GEMM chain || CSR chain, join before att1 ----------------
extern "C" void kernel_launch(void* const* d_in, const int* in_sizes, int n_in,
                              void* d_out, int out_size) {
    const float* x        = (const float*)d_in[0];
    const float* Wl1      = (const float*)d_in[2];
    const float* Wr1      = (const float*)d_in[3];
    const float* att1     = (const float*)d_in[4];
    const float* b1       = (const float*)d_in[5];
    const float* Wlin1    = (const float*)d_in[6];
    const float* blin1    = (const float*)d_in[7];
    const float* Wl2      = (const float*)d_in[8];
    const float* Wr2      = (const float*)d_in[9];
    const float* att2     = (const float*)d_in[10];
    const float* b2       = (const float*)d_in[11];
    const float* Wlin2    = (const float*)d_in[12];
    const float* blin2    = (const float*)d_in[13];
    float* out = (float*)d_out;

    long long tail_elems = (long long)out_size - (long long)Nn * 2;

    cudaFuncSetAttribute(k_gemm1, cudaFuncAttributeMaxDynamicSharedMemorySize, G1_SMEM);

    int nb = (Nn + 1023) / 1024;   // 98

    // Fork a side stream for the GEMM (independent of CSR build).
    cudaStream_t s2;
    cudaStreamCreateWithFlags(&s2, cudaStreamNonBlocking);
    cudaEvent_t evFork, evJoin;
    cudaEventCreateWithFlags(&evFork, cudaEventDisableTiming);
    cudaEventCreateWithFlags(&evJoin, cudaEventDisableTiming);

    cudaEventRecord(evFork, 0);
    cudaStreamWaitEvent(s2, evFork, 0);

    // side stream: the big dense transform only (critical-path minimal)
    k_gemm1<<<152, G1_THREADS, G1_SMEM, s2>>>(x, Wl1, Wr1, Wlin1, blin1);
    cudaEventRecord(evJoin, s2);

    // main stream: CSR build chain, then output tail (both shadowed by gemm1)
    k_init_deg<<<(Nn + 255) / 256, 256>>>();
    k_deg<<<(Ee + 255) / 256, 256>>>((const int*)d_in[1]);
    k_scan1<<<nb, 1024>>>();
    k_scan2<<<1, 128>>>(nb);
    k_scan3<<<(Nn + 255) / 256, 256>>>();
    k_scatter<<<(ET + 255) / 256, 256>>>((const int*)d_in[1]);
    if (tail_elems > 0) {
        int n = (tail_elems < (long long)2 * Ee) ? (int)tail_elems : 2 * Ee;
        k_cast_edges<<<(n + 255) / 256, 256>>>(
            (const int*)d_in[1], out + (size_t)Nn * 2, n);
    }

    // join: attention needs both GEMM outputs and CSR
    cudaStreamWaitEvent(0, evJoin, 0);
    k_att1<<<(Nn * 32 + 255) / 256, 256>>>(att1, b1, Wl2, Wr2, Wlin2, blin2);
    k_att2<<<(Nn * 32 + 255) / 256, 256>>>(att2, b2, out);

    cudaEventDestroy(evFork);
    cudaEventDestroy(evJoin);
    cudaStreamDestroy(s2);
}

// round 13
// speedup vs baseline: 1.2198x; 1.2198x over previous
#include <cuda_runtime.h>
#include <cuda_bf16.h>
#include <math.h>

// Problem constants (from reference)
constexpr int Nn  = 100000;
constexpr int Ee  = 3200000;
constexpr int ET  = Nn + Ee;       // edges + self loops
constexpr int FIN = 165;
constexpr int HID = 64;

// ---------------- scratch (static device allocations; no cudaMalloc) ----------------
__device__ float g_xl1[(size_t)Nn * HID];
__device__ float g_xr1[(size_t)Nn * HID];
__device__ float g_h  [(size_t)Nn * HID];   // x@Wlin1+blin1 (lin skip)
__device__ float g_xl2[Nn * 2];
__device__ float g_xr2[Nn * 2];
__device__ float g_lin2[Nn * 2];
__device__ int   g_deg[Nn];
__device__ int   g_incl[Nn];
__device__ int   g_rowptr[Nn + 1];
__device__ int   g_cursor[Nn];
__device__ int   g_bsum[128];
__device__ int   g_boff[128];
__device__ int   g_col[ET];

// ---------------- K0: init degrees (self loop => start at 1) ----------------
__global__ void k_init_deg() {
    int i = blockIdx.x * blockDim.x + threadIdx.x;
    if (i < Nn) g_deg[i] = 1;
}

// ---------------- K1: fused layer-1 triple GEMM — tensor cores (split-bf16 x3) ----------------
// xl1 = x@Wl1, xr1 = x@Wr1, h = x@Wlin1 + blin1, computed as one [100000 x 165] @ [165 x 192]
// GEMM via mma.sync.m16n8k16.bf16 with 3-term split: xh*Wh + xl*Wh + xh*Wl (err ~8e-6).
constexpr int KP     = 176;        // K padded to 11 k-steps of 16
constexpr int KPITCH = 184;        // smem row pitch (bf16 elems) — staggers banks
constexpr int G1_NT  = 1563;       // ceil(100000/64)
constexpr int G1_SMEM = (2 * 192 * KPITCH + 2 * 64 * KPITCH) * 2;  // 188,416 B

#define MMA_BF16(c0, c1, c2, c3, a0, a1, a2, a3, b0, b1) \
    asm volatile("mma.sync.aligned.m16n8k16.row.col.f32.bf16.bf16.f32 " \
        "{%0,%1,%2,%3},{%4,%5,%6,%7},{%8,%9},{%0,%1,%2,%3};" \
        : "+f"(c0), "+f"(c1), "+f"(c2), "+f"(c3) \
        : "r"(a0), "r"(a1), "r"(a2), "r"(a3), "r"(b0), "r"(b1))

__global__ __launch_bounds__(256, 1)
void k_gemm1(const float* __restrict__ x,
             const float* __restrict__ Wl, const float* __restrict__ Wr,
             const float* __restrict__ Wlin, const float* __restrict__ blin) {
    extern __shared__ char smem[];
    __nv_bfloat16* Wth = (__nv_bfloat16*)smem;           // [192][KPITCH] (n-major, k contiguous)
    __nv_bfloat16* Wtl = Wth + 192 * KPITCH;
    __nv_bfloat16* Xh  = Wtl + 192 * KPITCH;             // [64][KPITCH]
    __nv_bfloat16* Xl  = Xh + 64 * KPITCH;
    int tid = threadIdx.x;

    // W split + transpose into smem (once per block)
    for (int idx = tid; idx < 192 * KP; idx += 256) {
        int n = idx / KP, k = idx % KP;
        float v = 0.f;
        if (k < FIN) v = (n < 64) ? Wl[k * 64 + n]
                       : (n < 128) ? Wr[k * 64 + (n - 64)]
                       : Wlin[k * 64 + (n - 128)];
        __nv_bfloat16 h = __float2bfloat16(v);
        __nv_bfloat16 l = __float2bfloat16(v - __bfloat162float(h));
        Wth[n * KPITCH + k] = h;
        Wtl[n * KPITCH + k] = l;
    }

    int lane = tid & 31, w = tid >> 5;
    int mgroup = w & 1;            // 2 row-bands of 32
    int ngroup = w >> 1;           // 4 col-bands of 48
    int n0 = ngroup * 48;
    int lq = lane >> 2;            // lane/4
    int colb = 2 * (lane & 3);     // 2*(lane%4)

    // per-j destination pointer + bias (fixed across tiles)
    float* dstp[6];
    float2 biasj[6];
#pragma unroll
    for (int j = 0; j < 6; j++) {
        int col = n0 + j * 8 + colb;
        int reg = col >> 6, cc = col & 63;
        dstp[j] = ((reg == 0) ? g_xl1 : (reg == 1) ? g_xr1 : g_h) + cc;
        biasj[j] = (reg == 2) ? make_float2(blin[cc], blin[cc + 1]) : make_float2(0.f, 0.f);
    }

    for (int tile = blockIdx.x; tile < G1_NT; tile += gridDim.x) {
        int row0 = tile * 64;
        int rows = (Nn - row0 < 64) ? (Nn - row0) : 64;
        __syncthreads();   // previous k-loop done before X overwrite (also fences W fill)

        // X tile split into smem
        for (int idx = tid; idx < 64 * KP; idx += 256) {
            int rr = idx / KP, k = idx % KP;
            float v = (rr < rows && k < FIN) ? x[(size_t)(row0 + rr) * FIN + k] : 0.f;
            __nv_bfloat16 h = __float2bfloat16(v);
            __nv_bfloat16 l = __float2bfloat16(v - __bfloat162float(h));
            Xh[rr * KPITCH + k] = h;
            Xl[rr * KPITCH + k] = l;
        }
        __syncthreads();

        float c[2][6][4];
#pragma unroll
        for (int mt = 0; mt < 2; mt++)
#pragma unroll
            for (int j = 0; j < 6; j++)
#pragma unroll
                for (int q = 0; q < 4; q++) c[mt][j][q] = 0.f;

#pragma unroll
        for (int ks = 0; ks < KP / 16; ks++) {
            int k0 = ks * 16;
            unsigned ah[2][4], al[2][4];
#pragma unroll
            for (int mt = 0; mt < 2; mt++) {
                int r1 = (mgroup * 32 + mt * 16 + lq) * KPITCH + k0 + colb;
                int r2 = r1 + 8 * KPITCH;
                ah[mt][0] = *(const unsigned*)&Xh[r1];
                ah[mt][1] = *(const unsigned*)&Xh[r2];
                ah[mt][2] = *(const unsigned*)&Xh[r1 + 8];
                ah[mt][3] = *(const unsigned*)&Xh[r2 + 8];
                al[mt][0] = *(const unsigned*)&Xl[r1];
                al[mt][1] = *(const unsigned*)&Xl[r2];
                al[mt][2] = *(const unsigned*)&Xl[r1 + 8];
                al[mt][3] = *(const unsigned*)&Xl[r2 + 8];
            }
#pragma unroll
            for (int j = 0; j < 6; j++) {
                int nb = (n0 + j * 8 + lq) * KPITCH + k0 + colb;
                unsigned bh0 = *(const unsigned*)&Wth[nb];
                unsigned bh1 = *(const unsigned*)&Wth[nb + 8];
                unsigned bl0 = *(const unsigned*)&Wtl[nb];
                unsigned bl1 = *(const unsigned*)&Wtl[nb + 8];
#pragma unroll
                for (int mt = 0; mt < 2; mt++) {
                    MMA_BF16(c[mt][j][0], c[mt][j][1], c[mt][j][2], c[mt][j][3],
                             ah[mt][0], ah[mt][1], ah[mt][2], ah[mt][3], bh0, bh1);
                    MMA_BF16(c[mt][j][0], c[mt][j][1], c[mt][j][2], c[mt][j][3],
                             al[mt][0], al[mt][1], al[mt][2], al[mt][3], bh0, bh1);
                    MMA_BF16(c[mt][j][0], c[mt][j][1], c[mt][j][2], c[mt][j][3],
                             ah[mt][0], ah[mt][1], ah[mt][2], ah[mt][3], bl0, bl1);
                }
            }
        }

        // epilogue: c0,c1 -> row, c2,c3 -> row+8 (cols col, col+1)
#pragma unroll
        for (int mt = 0; mt < 2; mt++) {
            int rowa = row0 + mgroup * 32 + mt * 16 + lq;
#pragma unroll
            for (int j = 0; j < 6; j++) {
                if (rowa < Nn)
                    *(float2*)(dstp[j] + (size_t)rowa * 64) =
                        make_float2(c[mt][j][0] + biasj[j].x, c[mt][j][1] + biasj[j].y);
                if (rowa + 8 < Nn)
                    *(float2*)(dstp[j] + (size_t)(rowa + 8) * 64) =
                        make_float2(c[mt][j][2] + biasj[j].x, c[mt][j][3] + biasj[j].y);
            }
        }
    }
}

// ---------------- K2: degree histogram over real edges ----------------
__global__ void k_deg(const int* __restrict__ ei) {
    int i = blockIdx.x * blockDim.x + threadIdx.x;
    if (i < Ee) {
        int d = ei[Ee + i];     // dst row
        atomicAdd(&g_deg[d], 1);
    }
}

// ---------------- K3: 3-phase exclusive scan -> rowptr, cursor ----------------
__global__ __launch_bounds__(1024) void k_scan1() {
    __shared__ int s[1024];
    int tid = threadIdx.x;
    int i = blockIdx.x * 1024 + tid;
    int v = (i < Nn) ? g_deg[i] : 0;
    s[tid] = v;
    __syncthreads();
    for (int off = 1; off < 1024; off <<= 1) {
        int t = (tid >= off) ? s[tid - off] : 0;
        __syncthreads();
        s[tid] += t;
        __syncthreads();
    }
    if (i < Nn) g_incl[i] = s[tid];
    if (tid == 1023) g_bsum[blockIdx.x] = s[tid];
}

__global__ void k_scan2(int nb) {
    __shared__ int s[128];
    int tid = threadIdx.x;
    int v = (tid < nb) ? g_bsum[tid] : 0;
    s[tid] = v;
    __syncthreads();
    for (int off = 1; off < 128; off <<= 1) {
        int t = (tid >= off) ? s[tid - off] : 0;
        __syncthreads();
        s[tid] += t;
        __syncthreads();
    }
    g_boff[tid] = s[tid] - v;   // exclusive
}

__global__ void k_scan3() {
    int i = blockIdx.x * blockDim.x + threadIdx.x;
    if (i < Nn) {
        int r = g_incl[i] + g_boff[i >> 10];
        g_rowptr[i + 1] = r;
        g_cursor[i] = r - g_deg[i];    // == rowptr[i]
        if (i == 0) g_rowptr[0] = 0;
    }
}

// ---------------- K4: scatter edges + self loops into CSR ----------------
__global__ void k_scatter(const int* __restrict__ ei) {
    int i = blockIdx.x * blockDim.x + threadIdx.x;
    if (i >= ET) return;
    int s, d;
    if (i < Ee) { s = ei[i]; d = ei[Ee + i]; }
    else        { s = d = i - Ee; }
    int pos = atomicAdd(&g_cursor[d], 1);
    g_col[pos] = s;
}

// ---------------- K5: layer-1 attention + FUSED layer-2 transforms (R11) ----------------
__global__ __launch_bounds__(256, 5)
void k_att1(const float* __restrict__ att, const float* __restrict__ b1,
            const float* __restrict__ Wl2, const float* __restrict__ Wr2,
            const float* __restrict__ Wlin2, const float* __restrict__ blin2) {
    int gt = blockIdx.x * blockDim.x + threadIdx.x;
    int i = gt >> 5;
    int lane = gt & 31;
    if (i >= Nn) return;
    int half = lane >> 4;     // edge slot 0/1
    int g = lane & 15;        // channel group (4 channels)

    int e0 = g_rowptr[i], e1 = g_rowptr[i + 1];

    float4 r = ((const float4*)(g_xr1 + (size_t)i * 64))[g];
    float4 a = ((const float4*)att)[g];

    float m = -1e30f, s = 0.f;
    float A0 = 0.f, A1 = 0.f, A2 = 0.f, A3 = 0.f;

    for (int base = e0; base < e1; base += 2) {
        int idx = base + half;
        bool act = idx < e1;
        int j = act ? g_col[idx] : 0;
        float4 u = ((const float4*)(g_xl1 + (size_t)j * 64))[g];

        float t0 = u.x + r.x; t0 = (t0 > 0.f) ? t0 : 0.2f * t0;
        float t1 = u.y + r.y; t1 = (t1 > 0.f) ? t1 : 0.2f * t1;
        float t2 = u.z + r.z; t2 = (t2 > 0.f) ? t2 : 0.2f * t2;
        float t3 = u.w + r.w; t3 = (t3 > 0.f) ? t3 : 0.2f * t3;
        float p = t0 * a.x + t1 * a.y + t2 * a.z + t3 * a.w;
        p += __shfl_xor_sync(0xffffffffu, p, 1);
        p += __shfl_xor_sync(0xffffffffu, p, 2);
        p += __shfl_xor_sync(0xffffffffu, p, 4);
        p += __shfl_xor_sync(0xffffffffu, p, 8);

        if (act) {
            if (p > m) {
                float sc = __expf(m - p);
                s *= sc; A0 *= sc; A1 *= sc; A2 *= sc; A3 *= sc;
                m = p;
            }
            float w = __expf(p - m);
            s += w;
            A0 += w * u.x; A1 += w * u.y; A2 += w * u.z; A3 += w * u.w;
        }
    }

    // merge the two half-states (xor 16) — both halves end with identical state
    {
        float mo  = __shfl_xor_sync(0xffffffffu, m, 16);
        float so  = __shfl_xor_sync(0xffffffffu, s, 16);
        float B0  = __shfl_xor_sync(0xffffffffu, A0, 16);
        float B1  = __shfl_xor_sync(0xffffffffu, A1, 16);
        float B2  = __shfl_xor_sync(0xffffffffu, A2, 16);
        float B3  = __shfl_xor_sync(0xffffffffu, A3, 16);
        float mn = fmaxf(m, mo);
        float c1 = __expf(m - mn);
        float c2 = __expf(mo - mn);
        s  = s * c1 + so * c2;
        A0 = A0 * c1 + B0 * c2;
        A1 = A1 * c1 + B1 * c2;
        A2 = A2 * c1 + B2 * c2;
        A3 = A3 * c1 + B3 * c2;
    }

    float inv = 1.0f / s;
    float4 bb = ((const float4*)b1)[g];
    float4 hl = ((const float4*)(g_h + (size_t)i * 64))[g];
    float o0 = A0 * inv + bb.x + hl.x;
    float o1 = A1 * inv + bb.y + hl.y;
    float o2 = A2 * inv + bb.z + hl.z;
    float o3 = A3 * inv + bb.w + hl.w;
    o0 = (o0 > 0.f) ? o0 : (__expf(o0) - 1.0f);   // ELU
    o1 = (o1 > 0.f) ? o1 : (__expf(o1) - 1.0f);
    o2 = (o2 > 0.f) ? o2 : (__expf(o2) - 1.0f);
    o3 = (o3 > 0.f) ? o3 : (__expf(o3) - 1.0f);

    // fused layer-2 transforms: partial dots over this lane's 4 channels
    const float2* WlV = (const float2*)Wl2;
    const float2* WrV = (const float2*)Wr2;
    const float2* WnV = (const float2*)Wlin2;
    int c = g * 4;
    float2 wl0 = WlV[c], wl1 = WlV[c + 1], wl2v = WlV[c + 2], wl3 = WlV[c + 3];
    float2 wr0 = WrV[c], wr1 = WrV[c + 1], wr2v = WrV[c + 2], wr3 = WrV[c + 3];
    float2 wn0 = WnV[c], wn1 = WnV[c + 1], wn2v = WnV[c + 2], wn3 = WnV[c + 3];
    float xl_0 = o0 * wl0.x + o1 * wl1.x + o2 * wl2v.x + o3 * wl3.x;
    float xl_1 = o0 * wl0.y + o1 * wl1.y + o2 * wl2v.y + o3 * wl3.y;
    float xr_0 = o0 * wr0.x + o1 * wr1.x + o2 * wr2v.x + o3 * wr3.x;
    float xr_1 = o0 * wr0.y + o1 * wr1.y + o2 * wr2v.y + o3 * wr3.y;
    float ln_0 = o0 * wn0.x + o1 * wn1.x + o2 * wn2v.x + o3 * wn3.x;
    float ln_1 = o0 * wn0.y + o1 * wn1.y + o2 * wn2v.y + o3 * wn3.y;
#pragma unroll
    for (int o = 1; o <= 8; o <<= 1) {
        xl_0 += __shfl_xor_sync(0xffffffffu, xl_0, o);
        xl_1 += __shfl_xor_sync(0xffffffffu, xl_1, o);
        xr_0 += __shfl_xor_sync(0xffffffffu, xr_0, o);
        xr_1 += __shfl_xor_sync(0xffffffffu, xr_1, o);
        ln_0 += __shfl_xor_sync(0xffffffffu, ln_0, o);
        ln_1 += __shfl_xor_sync(0xffffffffu, ln_1, o);
    }
    if (lane == 0) {
        ((float2*)g_xl2)[i] = make_float2(xl_0, xl_1);
        ((float2*)g_xr2)[i] = make_float2(xr_0, xr_1);
        ((float2*)g_lin2)[i] = make_float2(ln_0 + blin2[0], ln_1 + blin2[1]);
    }
}

// ---------------- K7: layer-2 attention, SINGLE PASS + log_softmax ----------------
__global__ void k_att2(const float* __restrict__ att2, const float* __restrict__ b2,
                       float* __restrict__ out) {
    int gt = blockIdx.x * blockDim.x + threadIdx.x;
    int i = gt >> 5;
    int lane = gt & 31;
    if (i >= Nn) return;

    int e0 = g_rowptr[i], e1 = g_rowptr[i + 1];
    const float2* xl2v = (const float2*)g_xl2;
    float2 xr = ((const float2*)g_xr2)[i];
    float a0 = att2[0], a1 = att2[1];

    float m = -1e30f, s = 0.f, A0 = 0.f, A1 = 0.f;
    for (int base = e0; base < e1; base += 32) {
        int idx = base + lane;
        if (idx < e1) {
            int j = g_col[idx];
            float2 xj = xl2v[j];
            float h0 = xj.x + xr.x; h0 = (h0 > 0.f) ? h0 : 0.2f * h0;
            float h1 = xj.y + xr.y; h1 = (h1 > 0.f) ? h1 : 0.2f * h1;
            float e = a0 * h0 + a1 * h1;
            if (e > m) { float sc = __expf(m - e); s *= sc; A0 *= sc; A1 *= sc; m = e; }
            float w = __expf(e - m);
            s += w; A0 += w * xj.x; A1 += w * xj.y;
        }
    }
#pragma unroll
    for (int o = 16; o; o >>= 1) {
        float mo  = __shfl_xor_sync(0xffffffffu, m, o);
        float so  = __shfl_xor_sync(0xffffffffu, s, o);
        float A0o = __shfl_xor_sync(0xffffffffu, A0, o);
        float A1o = __shfl_xor_sync(0xffffffffu, A1, o);
        float mn = fmaxf(m, mo);
        float sc1 = __expf(m - mn);
        float sc2 = __expf(mo - mn);
        s  = s * sc1 + so * sc2;
        A0 = A0 * sc1 + A0o * sc2;
        A1 = A1 * sc1 + A1o * sc2;
        m = mn;
    }

    if (lane == 0) {
        float inv = 1.0f / s;
        float2 ln = ((const float2*)g_lin2)[i];
        float z0 = A0 * inv + b2[0] + ln.x;
        float z1 = A1 * inv + b2[1] + ln.y;
        float zm = fmaxf(z0, z1);
        float l = zm + __logf(__expf(z0 - zm) + __expf(z1 - zm));
        ((float2*)out)[i] = make_float2(z0 - l, z1 - l);
    }
}

// ---------------- K8: edge_index passthrough as float32 values ----------------
__global__ void k_cast_edges(const int* __restrict__ ei, float* __restrict__ out, int n) {
    int i = blockIdx.x * blockDim.x + threadIdx.x;
    if (i < n) out[i] = (float)ei[i];
}

// ---------------- launcher: fork GEMM chain || CSR chain, join before att1 ----------------
extern "C" void kernel_launch(void* const* d_in, const int* in_sizes, int n_in,
                              void* d_out, int out_size) {
    const float* x        = (const float*)d_in[0];
    const float* Wl1      = (const float*)d_in[2];
    const float* Wr1      = (const float*)d_in[3];
    const float* att1     = (const float*)d_in[4];
    const float* b1       = (const float*)d_in[5];
    const float* Wlin1    = (const float*)d_in[6];
    const float* blin1    = (const float*)d_in[7];
    const float* Wl2      = (const float*)d_in[8];
    const float* Wr2      = (const float*)d_in[9];
    const float* att2     = (const float*)d_in[10];
    const float* b2       = (const float*)d_in[11];
    const float* Wlin2    = (const float*)d_in[12];
    const float* blin2    = (const float*)d_in[13];
    float* out = (float*)d_out;

    long long tail_elems = (long long)out_size - (long long)Nn * 2;

    cudaFuncSetAttribute(k_gemm1, cudaFuncAttributeMaxDynamicSharedMemorySize, G1_SMEM);

    int nb = (Nn + 1023) / 1024;   // 98

    // Fork a side stream for the GEMM (independent of CSR build).
    cudaStream_t s2;
    cudaStreamCreateWithFlags(&s2, cudaStreamNonBlocking);
    cudaEvent_t evFork, evJoin;
    cudaEventCreateWithFlags(&evFork, cudaEventDisableTiming);
    cudaEventCreateWithFlags(&evJoin, cudaEventDisableTiming);

    cudaEventRecord(evFork, 0);
    cudaStreamWaitEvent(s2, evFork, 0);

    // side stream: tensor-core GEMM
    k_gemm1<<<152, 256, G1_SMEM, s2>>>(x, Wl1, Wr1, Wlin1, blin1);
    cudaEventRecord(evJoin, s2);

    // main stream: CSR build chain, then output tail (shadowed by gemm1/CSR)
    k_init_deg<<<(Nn + 255) / 256, 256>>>();
    k_deg<<<(Ee + 255) / 256, 256>>>((const int*)d_in[1]);
    k_scan1<<<nb, 1024>>>();
    k_scan2<<<1, 128>>>(nb);
    k_scan3<<<(Nn + 255) / 256, 256>>>();
    k_scatter<<<(ET + 255) / 256, 256>>>((const int*)d_in[1]);
    if (tail_elems > 0) {
        int n = (tail_elems < (long long)2 * Ee) ? (int)tail_elems : 2 * Ee;
        k_cast_edges<<<(n + 255) / 256, 256>>>(
            (const int*)d_in[1], out + (size_t)Nn * 2, n);
    }

    // join: attention needs both GEMM outputs and CSR
    cudaStreamWaitEvent(0, evJoin, 0);
    k_att1<<<(Nn * 32 + 255) / 256, 256>>>(att1, b1, Wl2, Wr2, Wlin2, blin2);
    k_att2<<<(Nn * 32 + 255) / 256, 256>>>(att2, b2, out);

    cudaEventDestroy(evFork);
    cudaEventDestroy(evJoin);
    cudaStreamDestroy(s2);
}